// round 13
// baseline (speedup 1.0000x reference)
#include <cuda_runtime.h>
#include <cuda_bf16.h>
#include <cstddef>

// Problem constants (fixed by the reference setup)
#define BB      16
#define TRED    512
#define CC      512
#define C4      (CC / 4)   // float4 per row = 128
#define TT      64         // t-rows per block
#define NTH     512        // threads per block
#define NWARP   (NTH / 32) // 16

// One fused kernel.
//   head (cheap): 512-wide inclusive scan of durations[b] via warp shfl scans
//                 (3 __syncthreads total), binary search seg for TT rows, mask.
//   body (hot)  : float4 streamed gather px[b,seg,:] -> out[b,t,:], __stcs
//                 evict-first stores so the 137MB write stream doesn't evict
//                 the 16.8MB gather source from L2.
__global__ __launch_bounds__(NTH)
void upsample_fused(const float* __restrict__ px,
                    const int*   __restrict__ dur,
                    const int*   __restrict__ target_T,
                    float*       __restrict__ out,
                    int max_len, int write_mask)
{
    __shared__ int csum[TRED];
    __shared__ int wsum[NWARP];
    __shared__ int seg_s[TT];

    const int b    = blockIdx.y;
    const int tid  = threadIdx.x;
    const int lane = tid & 31;
    const int wid  = tid >> 5;
    const int t0   = blockIdx.x * TT;

    // ---- inclusive scan of durations[b] (warp shfl scan, 3 syncs) ----
    int x = dur[b * TRED + tid];
    #pragma unroll
    for (int off = 1; off < 32; off <<= 1) {
        int y = __shfl_up_sync(0xffffffffu, x, off);
        if (lane >= off) x += y;
    }
    if (lane == 31) wsum[wid] = x;
    __syncthreads();
    if (wid == 0) {
        int w = (lane < NWARP) ? wsum[lane] : 0;
        #pragma unroll
        for (int off = 1; off < NWARP; off <<= 1) {
            int y = __shfl_up_sync(0xffffffffu, w, off);
            if (lane >= off) w += y;
        }
        if (lane < NWARP) wsum[lane] = w;
    }
    __syncthreads();
    csum[tid] = x + ((wid > 0) ? wsum[wid - 1] : 0);
    __syncthreads();

    const int total    = csum[TRED - 1];
    const int curr_len = min(total, target_T[b]);   // == total by construction

    // ---- first TT threads: searchsorted + mask write ----
    if (tid < TT) {
        const int t     = t0 + tid;
        const int valid = (t < max_len) && (t < curr_len);
        int seg = -1;
        if (valid) {
            int lo = 0, hi = TRED;                   // first i with csum[i] > t
            while (lo < hi) {
                int mid = (lo + hi) >> 1;
                if (csum[mid] > t) hi = mid; else lo = mid + 1;
            }
            seg = min(lo, TRED - 1);
        }
        seg_s[tid] = seg;
        if (write_mask && t < max_len) {
            float* mask = out + (size_t)BB * max_len * CC;
            __stcs(&mask[(size_t)b * max_len + t], valid ? 0.0f : 1.0f);
        }
    }
    __syncthreads();

    // ---- hot loop: 128 threads per t-row, 4 rows per wave, 16 waves ----
    const int row = tid >> 7;        // 0..3
    const int c4  = tid & (C4 - 1);  // 0..127
    const float4* px4  = (const float4*)px;
    float4*       out4 = (float4*)out;

    #pragma unroll
    for (int r = row; r < TT; r += NTH / C4) {
        const int t = t0 + r;
        if (t >= max_len) continue;
        const int s = seg_s[r];
        float4 v;
        if (s >= 0) {
            v = __ldg(&px4[((size_t)b * TRED + s) * C4 + c4]);
        } else {
            v = make_float4(0.0f, 0.0f, 0.0f, 0.0f);
        }
        __stcs(&out4[((size_t)b * max_len + t) * C4 + c4], v);
    }
}

extern "C" void kernel_launch(void* const* d_in, const int* in_sizes, int n_in,
                              void* d_out, int out_size)
{
    const float* px  = (const float*)d_in[0];   // pooled_x  (B, T_RED, C) f32
    const int*   dur = (const int*)  d_in[1];   // durations (B, T_RED)   i32
    const int*   tgt = (const int*)  d_in[2];   // target_T  (B,)         i32

    // Recover max_len from out_size. Layout: [x (B*max_len*C)] ++ [mask (B*max_len)].
    int max_len, write_mask;
    if (out_size % (BB * (CC + 1)) == 0) {
        max_len    = out_size / (BB * (CC + 1));
        write_mask = 1;
    } else {
        max_len    = out_size / (BB * CC);   // fallback: x-only output
        write_mask = 0;
    }

    dim3 grid((max_len + TT - 1) / TT, BB);
    upsample_fused<<<grid, NTH>>>(px, dur, tgt, (float*)d_out, max_len, write_mask);
}